// round 17
// baseline (speedup 1.0000x reference)
#include <cuda_runtime.h>
#include <cuda_fp16.h>
#include <math.h>
#include <stdint.h>

// ---------------- static config ----------------
#define B_   8
#define H_   80
#define W_   60
#define C_   512
#define WS_  10
#define SHIFT_ 5
#define NH_  16
#define HD_  32
#define L_   100
#define NWH_ 8
#define NWW_ 6
#define NW_  48
#define TOK_ (B_*H_*W_)    // 38400
#define FF_  2048

// ---------------- scratch ----------------
__device__ __half g_ah[(size_t)TOK_*C_];
__device__ __half g_qh[(size_t)TOK_*C_];
__device__ __half g_kh[(size_t)TOK_*C_];
__device__ __half g_vh[(size_t)TOK_*C_];
__device__ __half g_ch[(size_t)TOK_*C_];
__device__ float  g_hs[(size_t)TOK_*C_];
__device__ __half g_fh[(size_t)TOK_*FF_];
__device__ __half g_wh[3145728];
__device__ float  g_bqkv[3*C_];

// ---------------- helpers ----------------
__device__ __forceinline__ uint32_t smem_u32(const void* p) {
    uint32_t a;
    asm("{ .reg .u64 t; cvta.to.shared.u64 t, %1; cvt.u32.u64 %0, t; }" : "=r"(a) : "l"(p));
    return a;
}
__device__ __forceinline__ void cp16(uint32_t s, const void* g) {
    asm volatile("cp.async.cg.shared.global [%0], [%1], 16;" :: "r"(s), "l"(g) : "memory");
}
__device__ __forceinline__ void mma_f16(float* d, const uint32_t* a, const uint32_t* b) {
    asm volatile(
        "mma.sync.aligned.m16n8k16.row.col.f32.f16.f16.f32 "
        "{%0,%1,%2,%3}, {%4,%5,%6,%7}, {%8,%9}, {%0,%1,%2,%3};"
        : "+f"(d[0]), "+f"(d[1]), "+f"(d[2]), "+f"(d[3])
        : "r"(a[0]), "r"(a[1]), "r"(a[2]), "r"(a[3]), "r"(b[0]), "r"(b[1]));
}
__device__ __forceinline__ void ldsm4(uint32_t* r, uint32_t addr) {
    asm volatile("ldmatrix.sync.aligned.m8n8.x4.shared.b16 {%0,%1,%2,%3}, [%4];"
                 : "=r"(r[0]), "=r"(r[1]), "=r"(r[2]), "=r"(r[3]) : "r"(addr));
}
__device__ __forceinline__ uint32_t pack_h2(float a, float b) {
    __half2 h = __floats2half2_rn(a, b);
    return *(uint32_t*)&h;
}

// ---------------- merged weight/bias conversion -----------------------------
// segments: wq,wk,wv (into whqkv Ntot=1536), wo, w1, w2, bias-concat
#define CW_TOT (4*C_*C_ + 2*C_*FF_ + 3*C_)
__global__ __launch_bounds__(256) void convall_kernel(
    const float* __restrict__ wq, const float* __restrict__ wk,
    const float* __restrict__ wv, const float* __restrict__ wo,
    const float* __restrict__ w1, const float* __restrict__ w2,
    const float* __restrict__ bq, const float* __restrict__ bk,
    const float* __restrict__ bv,
    __half* __restrict__ whqkv, __half* __restrict__ who,
    __half* __restrict__ wh1, __half* __restrict__ wh2,
    float* __restrict__ bqkv)
{
    int idx = blockIdx.x * 256 + threadIdx.x;
    if (idx >= CW_TOT) return;
    const int S = C_ * C_;              // 262144
    if (idx < 3 * S) {
        int seg = idx / S, r = idx - seg * S;
        const float* w = (seg == 0) ? wq : (seg == 1) ? wk : wv;
        int k = r >> 9, n = r & 511;
        whqkv[(size_t)(k >> 1) * 3072 + 2 * (seg * C_ + n) + (k & 1)] = __float2half(w[r]);
    } else if (idx < 4 * S) {
        int r = idx - 3 * S;
        int k = r >> 9, n = r & 511;
        who[(size_t)(k >> 1) * 1024 + 2 * n + (k & 1)] = __float2half(wo[r]);
    } else if (idx < 4 * S + C_ * FF_) {
        int r = idx - 4 * S;
        int k = r >> 11, n = r & 2047;
        wh1[(size_t)(k >> 1) * 4096 + 2 * n + (k & 1)] = __float2half(w1[r]);
    } else if (idx < 4 * S + 2 * C_ * FF_) {
        int r = idx - 4 * S - C_ * FF_;
        int k = r >> 9, n = r & 511;
        wh2[(size_t)(k >> 1) * 1024 + 2 * n + (k & 1)] = __float2half(w2[r]);
    } else {
        int r = idx - 4 * S - 2 * C_ * FF_;
        int seg = r >> 9, n = r & 511;
        bqkv[r] = (seg == 0) ? bq[n] : (seg == 1) ? bk[n] : bv[n];
    }
}

// ---------------- block reduction ----------------
__device__ __forceinline__ float block_sum_128(float v) {
    #pragma unroll
    for (int o = 16; o > 0; o >>= 1) v += __shfl_xor_sync(0xffffffffu, v, o);
    __shared__ float sh[4];
    int lane = threadIdx.x & 31, wid = threadIdx.x >> 5;
    __syncthreads();
    if (lane == 0) sh[wid] = v;
    __syncthreads();
    return sh[0] + sh[1] + sh[2] + sh[3];
}

// ---------------- LN (remap=1: LN1 + shift + window partition) --------------
__global__ __launch_bounds__(128) void ln_kernel(
    const float* __restrict__ x, const float* __restrict__ g,
    const float* __restrict__ bt, __half* __restrict__ out, int remap)
{
    int r = blockIdx.x;
    size_t in_row;
    if (remap) {
        int wg = r / L_, l = r % L_;
        int b = wg / NW_, wi = wg % NW_;
        int wh = wi / NWW_, ww = wi % NWW_;
        int h = (wh * WS_ + l / WS_ + SHIFT_) % H_;
        int w = (ww * WS_ + l % WS_ + SHIFT_) % W_;
        in_row = (size_t)b * (H_ * W_) + h * W_ + w;
    } else in_row = r;

    const float* row = x + in_row * C_;
    float v[4]; float s = 0.f;
    #pragma unroll
    for (int e = 0; e < 4; e++) { v[e] = row[threadIdx.x + e * 128]; s += v[e]; }
    float mean = block_sum_128(s) * (1.f / C_);
    float d2 = 0.f;
    #pragma unroll
    for (int e = 0; e < 4; e++) { float d = v[e] - mean; d2 += d * d; }
    float var = block_sum_128(d2) * (1.f / C_);
    float rstd = rsqrtf(var + 1e-5f);
    __half* o = out + (size_t)r * C_;
    #pragma unroll
    for (int e = 0; e < 4; e++) {
        int c = threadIdx.x + e * 128;
        o[c] = __float2half((v[e] - mean) * rstd * g[c] + bt[c]);
    }
}

// ---------------- fp16 mma.sync GEMM (ldmatrix A, 4-stage) ------------------
// epi: 0 f32; 1 half+GELU; 2 f32+res; 3 half qkv split; 4 permute+residual->hs
#define BM 128
#define BN 128
#define BK 32
#define ASW 36
#define BSW 136
#define STG_W (BM * ASW + 16 * BSW)

__global__ __launch_bounds__(256, 2) void gemm_h(
    const __half* __restrict__ Ah, const __half* __restrict__ Wh,
    const float* __restrict__ bias, const float* __restrict__ res,
    void* __restrict__ outp, int Nout, int K, int epi,
    void* __restrict__ out2, void* __restrict__ out3)
{
    extern __shared__ uint32_t sm[];

    int tid = threadIdx.x, lane = tid & 31, wid = tid >> 5;
    int tok0 = blockIdx.x * BM, n0 = blockIdx.y * BN;
    int wm0 = (wid & 1) * 64, wn0 = (wid >> 1) * 32;

    int a_row = tid >> 2, a_seg = tid & 3;
    int b_row = tid >> 4, b_seg = tid & 15;
    const __half* a_gp = Ah + (size_t)(tok0 + a_row) * K + a_seg * 8;
    const __half* b_gp = Wh + (size_t)b_row * (2 * Nout) + n0 * 2 + b_seg * 8;

    float acc[4][4][4];
    #pragma unroll
    for (int mt = 0; mt < 4; mt++)
        #pragma unroll
        for (int nt = 0; nt < 4; nt++)
            #pragma unroll
            for (int e = 0; e < 4; e++) acc[mt][nt][e] = 0.f;

    const int nch = K / BK;

    auto issue = [&](int c) {
        int s = c & 3;
        uint32_t* Ab = sm + s * STG_W;
        uint32_t* Bb = Ab + BM * ASW;
        int k0 = c * BK;
        #pragma unroll
        for (int i = 0; i < 2; i++)
            cp16(smem_u32(Ab + (a_row + i * 64) * ASW + a_seg * 4),
                 a_gp + (size_t)(i * 64) * K + k0);
        #pragma unroll
        for (int i = 0; i < 2; i++)
            cp16(smem_u32(Bb + b_row * BSW + (b_seg + i * 16) * 4),
                 b_gp + (size_t)(k0 >> 1) * (2 * Nout) + i * 128);
        asm volatile("cp.async.commit_group;" ::: "memory");
    };

    issue(0);
    issue(1);
    issue(2);

    int lrow = lane & 15, lkh = (lane >> 4) * 4;

    for (int c = 0; c < nch; c++) {
        if (c < nch - 2) {
            asm volatile("cp.async.wait_group 2;" ::: "memory");
        } else if (c < nch - 1) {
            asm volatile("cp.async.wait_group 1;" ::: "memory");
        } else {
            asm volatile("cp.async.wait_group 0;" ::: "memory");
        }
        __syncthreads();
        if (c + 3 < nch) issue(c + 3);

        int s = c & 3;
        const uint32_t* A = sm + s * STG_W;
        const uint32_t* Bm = A + BM * ASW;
        int c4 = lane & 3, bn = lane >> 2;
        #pragma unroll
        for (int ks = 0; ks < 2; ks++) {
            uint32_t a[4][4], b[4][2];
            #pragma unroll
            for (int mt = 0; mt < 4; mt++) {
                uint32_t addr = smem_u32(A + (wm0 + mt * 16 + lrow) * ASW + ks * 8 + lkh);
                ldsm4(a[mt], addr);
            }
            int pb0 = (ks * 8 + c4) * BSW;
            int pb1 = (ks * 8 + c4 + 4) * BSW;
            #pragma unroll
            for (int nt = 0; nt < 4; nt++) {
                int n = wn0 + nt * 8 + bn;
                b[nt][0] = Bm[pb0 + n];
                b[nt][1] = Bm[pb1 + n];
            }
            #pragma unroll
            for (int mt = 0; mt < 4; mt++)
                #pragma unroll
                for (int nt = 0; nt < 4; nt++)
                    mma_f16(acc[mt][nt], a[mt], b[nt]);
        }
    }

    // ---- epilogue ----
    if (epi == 4) {
        // windowed row -> image row; hs[img] = acc + bias + hidden[img]
        float* hs = (float*)outp;
        #pragma unroll
        for (int mt = 0; mt < 4; mt++) {
            int r0 = tok0 + wm0 + mt * 16 + (lane >> 2);
            int img[2];
            #pragma unroll
            for (int h = 0; h < 2; h++) {
                int r = r0 + h * 8;
                int wg = r / L_, l = r - wg * L_;
                int b = wg / NW_, wi = wg - b * NW_;
                int wh = wi / NWW_, ww = wi - wh * NWW_;
                int hh = (wh * WS_ + l / WS_ + SHIFT_) % H_;
                int wcol = (ww * WS_ + l % WS_ + SHIFT_) % W_;
                img[h] = b * (H_ * W_) + hh * W_ + wcol;
            }
            #pragma unroll
            for (int nt = 0; nt < 4; nt++) {
                int c0 = n0 + wn0 + nt * 8 + 2 * (lane & 3);
                float2 bv = *(const float2*)(bias + c0);
                #pragma unroll
                for (int h = 0; h < 2; h++) {
                    float2 rr = *(const float2*)(res + (size_t)img[h] * C_ + c0);
                    float2 o;
                    o.x = acc[mt][nt][2 * h + 0] + bv.x + rr.x;
                    o.y = acc[mt][nt][2 * h + 1] + bv.y + rr.y;
                    *(float2*)(hs + (size_t)img[h] * C_ + c0) = o;
                }
            }
        }
        return;
    }

    __half* hsplit = nullptr;
    int ncol0 = n0;
    if (epi == 3) {
        int seg = n0 >> 9;
        hsplit = (seg == 0) ? (__half*)outp : (seg == 1) ? (__half*)out2 : (__half*)out3;
        ncol0 = n0 & 511;
    }
    #pragma unroll
    for (int mt = 0; mt < 4; mt++) {
        #pragma unroll
        for (int nt = 0; nt < 4; nt++) {
            int r0 = tok0 + wm0 + mt * 16 + (lane >> 2);
            int cg = n0 + wn0 + nt * 8 + 2 * (lane & 3);
            int c0 = ncol0 + wn0 + nt * 8 + 2 * (lane & 3);
            float2 bv = *(const float2*)(bias + cg);
            #pragma unroll
            for (int h = 0; h < 2; h++) {
                int row = r0 + h * 8;
                float v0 = acc[mt][nt][2 * h + 0] + bv.x;
                float v1 = acc[mt][nt][2 * h + 1] + bv.y;
                if (epi == 3) {
                    *(__half2*)(hsplit + (size_t)row * C_ + c0) = __floats2half2_rn(v0, v1);
                } else if (epi == 1) {
                    v0 = 0.5f * v0 * (1.f + erff(v0 * 0.70710678118654752f));
                    v1 = 0.5f * v1 * (1.f + erff(v1 * 0.70710678118654752f));
                    *(__half2*)((__half*)outp + (size_t)row * Nout + c0) =
                        __floats2half2_rn(v0, v1);
                } else {
                    if (epi == 2) {
                        float2 rr = *(const float2*)(res + (size_t)row * Nout + c0);
                        v0 += rr.x; v1 += rr.y;
                    }
                    float2 o; o.x = v0; o.y = v1;
                    *(float2*)((float*)outp + (size_t)row * Nout + c0) = o;
                }
            }
        }
    }
}

// ---------------- tensor-core windowed attention ----------------------------
__global__ __launch_bounds__(128) void attn_mma(
    const __half* __restrict__ Qh, const __half* __restrict__ Kh,
    const __half* __restrict__ Vh, const float* __restrict__ table,
    __half* __restrict__ ctx)
{
    int w = blockIdx.x, head = blockIdx.y;
    int wi = w % NW_;
    int whh = wi / NWW_, www = wi % NWW_;

    __shared__ __half Qs[128][40];
    __shared__ __half Ks[112][40];
    __shared__ __half Vt[32][120];
    __shared__ float stable[361];
    __shared__ int lab[100];

    int tid = threadIdx.x, lane = tid & 31, wid = tid >> 5;

    for (int i = tid; i < 560; i += 128) ((uint32_t*)Qs)[100 * 20 + i] = 0u;
    for (int i = tid; i < 240; i += 128) ((uint32_t*)Ks)[100 * 20 + i] = 0u;
    for (int i = tid; i < 320; i += 128) {
        int n = i / 10, c = i % 10;
        ((uint32_t*)Vt)[n * 60 + 50 + c] = 0u;
    }
    for (int idx = tid; idx < 400; idx += 128) {
        int l = idx >> 2, ch = idx & 3;
        size_t gi = (size_t)(w * L_ + l) * C_ + head * HD_ + ch * 8;
        *(int4*)&Qs[l][ch * 8] = *(const int4*)(Qh + gi);
        *(int4*)&Ks[l][ch * 8] = *(const int4*)(Kh + gi);
    }
    for (int idx = tid; idx < 800; idx += 128) {
        int p = idx >> 4, j = idx & 15;
        const __half2 a = *(const __half2*)(Vh + (size_t)(w * L_ + 2 * p) * C_ + head * HD_ + 2 * j);
        const __half2 b = *(const __half2*)(Vh + (size_t)(w * L_ + 2 * p + 1) * C_ + head * HD_ + 2 * j);
        *(__half2*)&Vt[2 * j][2 * p]     = __halves2half2(__low2half(a),  __low2half(b));
        *(__half2*)&Vt[2 * j + 1][2 * p] = __halves2half2(__high2half(a), __high2half(b));
    }
    for (int i = tid; i < 361; i += 128) stable[i] = table[i * NH_ + head];
    if (tid < 100) {
        int i = tid / WS_, j = tid % WS_;
        int h = whh * WS_ + i, x = www * WS_ + j;
        int rh = (h < H_ - WS_) ? 0 : ((h < H_ - SHIFT_) ? 1 : 2);
        int rw = (x < W_ - WS_) ? 0 : ((x < W_ - SHIFT_) ? 1 : 2);
        lab[tid] = rh * 3 + rw;
    }
    __syncthreads();

    const float scale = 0.17677669529663687f;
    int wm0 = wid * 32;
    int c4 = lane & 3, bn = lane >> 2;
    float ctxa[2][4][4];
    #pragma unroll
    for (int mt = 0; mt < 2; mt++)
        #pragma unroll
        for (int nt = 0; nt < 4; nt++)
            #pragma unroll
            for (int e = 0; e < 4; e++) ctxa[mt][nt][e] = 0.f;
    float inva[2][2];

    const uint32_t* Ks2 = (const uint32_t*)Ks;
    const uint32_t* Vt2 = (const uint32_t*)Vt;

    #pragma unroll
    for (int mt = 0; mt < 2; mt++) {
        float sacc[14][4];
        #pragma unroll
        for (int nt = 0; nt < 14; nt++)
            #pragma unroll
            for (int e = 0; e < 4; e++) sacc[nt][e] = 0.f;

        uint32_t afr[2][4];
        #pragma unroll
        for (int kk = 0; kk < 2; kk++) {
            uint32_t addr = smem_u32(&Qs[wm0 + mt * 16 + (lane & 15)][kk * 16 + (lane >> 4) * 8]);
            ldsm4(afr[kk], addr);
        }
        #pragma unroll
        for (int nt = 0; nt < 14; nt++) {
            int key = nt * 8 + bn;
            #pragma unroll
            for (int kk = 0; kk < 2; kk++) {
                uint32_t b[2];
                b[0] = Ks2[key * 20 + kk * 8 + c4];
                b[1] = Ks2[key * 20 + kk * 8 + c4 + 4];
                mma_f16(sacc[nt], afr[kk], b);
            }
        }

        int r0 = wm0 + mt * 16 + bn, r1 = r0 + 8;
        int r0c = (r0 < 100) ? r0 : 99;
        int r1c = (r1 < 100) ? r1 : 99;
        int i1a = r0c / 10, j1a = r0c - i1a * 10, la = lab[r0c];
        int i1b = r1c / 10, j1b = r1c - i1b * 10, lb = lab[r1c];

        float mx0 = -1e30f, mx1 = -1e30f;
        #pragma unroll
        for (int nt = 0; nt < 14; nt++) {
            int c0 = nt * 8 + 2 * c4;
            if (c0 >= 100) {
                sacc[nt][0] = sacc[nt][1] = sacc[nt][2] = sacc[nt][3] = -1e30f;
            } else {
                int i2a = c0 / 10, j2a = c0 - i2a * 10;
                int cc1 = c0 + 1;
                int i2b = cc1 / 10, j2b = cc1 - i2b * 10;
                int lc0 = lab[c0], lc1 = lab[cc1];
                float m00 = (lc0 != la) ? -100.f : 0.f;
                float m01 = (lc1 != la) ? -100.f : 0.f;
                float m10 = (lc0 != lb) ? -100.f : 0.f;
                float m11 = (lc1 != lb) ? -100.f : 0.f;
                float s0 = sacc[nt][0] * scale + stable[(i1a - i2a + 9) * 19 + (j1a - j2a + 9)] + m00;
                float s1 = sacc[nt][1] * scale + stable[(i1a - i2b + 9) * 19 + (j1a - j2b + 9)] + m01;
                float s2 = sacc[nt][2] * scale + stable[(i1b - i2a + 9) * 19 + (j1b - j2a + 9)] + m10;
                float s3 = sacc[nt][3] * scale + stable[(i1b - i2b + 9) * 19 + (j1b - j2b + 9)] + m11;
                sacc[nt][0] = s0; sacc[nt][1] = s1; sacc[nt][2] = s2; sacc[nt][3] = s3;
                mx0 = fmaxf(mx0, fmaxf(s0, s1));
                mx1 = fmaxf(mx1, fmaxf(s2, s3));
            }
        }
        mx0 = fmaxf(mx0, __shfl_xor_sync(0xffffffffu, mx0, 1));
        mx0 = fmaxf(mx0, __shfl_xor_sync(0xffffffffu, mx0, 2));
        mx1 = fmaxf(mx1, __shfl_xor_sync(0xffffffffu, mx1, 1));
        mx1 = fmaxf(mx1, __shfl_xor_sync(0xffffffffu, mx1, 2));

        float sum0 = 0.f, sum1 = 0.f;
        #pragma unroll
        for (int nt = 0; nt < 14; nt++) {
            float p0 = __expf(sacc[nt][0] - mx0);
            float p1 = __expf(sacc[nt][1] - mx0);
            float p2 = __expf(sacc[nt][2] - mx1);
            float p3 = __expf(sacc[nt][3] - mx1);
            sacc[nt][0] = p0; sacc[nt][1] = p1; sacc[nt][2] = p2; sacc[nt][3] = p3;
            sum0 += p0 + p1; sum1 += p2 + p3;
        }
        sum0 += __shfl_xor_sync(0xffffffffu, sum0, 1);
        sum0 += __shfl_xor_sync(0xffffffffu, sum0, 2);
        sum1 += __shfl_xor_sync(0xffffffffu, sum1, 1);
        sum1 += __shfl_xor_sync(0xffffffffu, sum1, 2);
        inva[mt][0] = 1.f / sum0;
        inva[mt][1] = 1.f / sum1;

        #pragma unroll
        for (int kt = 0; kt < 7; kt++) {
            uint32_t pa[4];
            pa[0] = pack_h2(sacc[2 * kt][0],     sacc[2 * kt][1]);
            pa[1] = pack_h2(sacc[2 * kt][2],     sacc[2 * kt][3]);
            pa[2] = pack_h2(sacc[2 * kt + 1][0], sacc[2 * kt + 1][1]);
            pa[3] = pack_h2(sacc[2 * kt + 1][2], sacc[2 * kt + 1][3]);
            #pragma unroll
            for (int nt2 = 0; nt2 < 4; nt2++) {
                int n = nt2 * 8 + bn;
                uint32_t b[2];
                b[0] = Vt2[n * 60 + kt * 8 + c4];
                b[1] = Vt2[n * 60 + kt * 8 + c4 + 4];
                mma_f16(ctxa[mt][nt2], pa, b);
            }
        }
    }

    #pragma unroll
    for (int mt = 0; mt < 2; mt++) {
        int r0 = wm0 + mt * 16 + bn, r1 = r0 + 8;
        #pragma unroll
        for (int nt2 = 0; nt2 < 4; nt2++) {
            int c = head * HD_ + nt2 * 8 + 2 * c4;
            if (r0 < 100)
                *(__half2*)(ctx + (size_t)(w * L_ + r0) * C_ + c) =
                    __floats2half2_rn(ctxa[mt][nt2][0] * inva[mt][0],
                                      ctxa[mt][nt2][1] * inva[mt][0]);
            if (r1 < 100)
                *(__half2*)(ctx + (size_t)(w * L_ + r1) * C_ + c) =
                    __floats2half2_rn(ctxa[mt][nt2][2] * inva[mt][1],
                                      ctxa[mt][nt2][3] * inva[mt][1]);
        }
    }
}

// ---------------- driver ----------------------------------------------------
extern "C" void kernel_launch(void* const* d_in, const int* in_sizes, int n_in,
                              void* d_out, int out_size)
{
    const float* hidden = (const float*)d_in[0];
    const float* ln1_g  = (const float*)d_in[1];
    const float* ln1_b  = (const float*)d_in[2];
    const float* wq = (const float*)d_in[3];
    const float* bq = (const float*)d_in[4];
    const float* wk = (const float*)d_in[5];
    const float* bk = (const float*)d_in[6];
    const float* wv = (const float*)d_in[7];
    const float* bv = (const float*)d_in[8];
    const float* wo = (const float*)d_in[9];
    const float* bo = (const float*)d_in[10];
    const float* table = (const float*)d_in[11];
    const float* ln2_g = (const float*)d_in[12];
    const float* ln2_b = (const float*)d_in[13];
    const float* w1 = (const float*)d_in[14];
    const float* b1 = (const float*)d_in[15];
    const float* w2 = (const float*)d_in[16];
    const float* b2 = (const float*)d_in[17];
    float* out = (float*)d_out;

    __half *pah, *pqh, *pkh, *pvh, *pch, *pfh, *pwh;
    float *phs, *pbqkv;
    cudaGetSymbolAddress((void**)&pah, g_ah);
    cudaGetSymbolAddress((void**)&pqh, g_qh);
    cudaGetSymbolAddress((void**)&pkh, g_kh);
    cudaGetSymbolAddress((void**)&pvh, g_vh);
    cudaGetSymbolAddress((void**)&pch, g_ch);
    cudaGetSymbolAddress((void**)&phs, g_hs);
    cudaGetSymbolAddress((void**)&pfh, g_fh);
    cudaGetSymbolAddress((void**)&pwh, g_wh);
    cudaGetSymbolAddress((void**)&pbqkv, g_bqkv);

    __half* whqkv = pwh;
    __half* who = pwh + 786432;
    __half* wh1 = pwh + 1048576;
    __half* wh2 = pwh + 2097152;

    const int GSMEM = 4 * STG_W * 4;  // 108544 bytes
    cudaFuncSetAttribute(gemm_h, cudaFuncAttributeMaxDynamicSharedMemorySize, GSMEM);

    // 0) merged weight/bias conversion
    convall_kernel<<<(CW_TOT + 255) / 256, 256>>>(wq, wk, wv, wo, w1, w2, bq, bk, bv,
                                                  whqkv, who, wh1, wh2, pbqkv);

    // 1) LN1 + shift + window partition -> g_ah
    ln_kernel<<<TOK_, 128>>>(hidden, ln1_g, ln1_b, pah, 1);

    // 2) fused QKV projection -> half q/k/v
    gemm_h<<<dim3(TOK_ / BM, (3 * C_) / BN), 256, GSMEM>>>(
        pah, whqkv, pbqkv, nullptr, pqh, 3 * C_, C_, 3, pkh, pvh);

    // 3) tensor-core windowed attention -> g_ch
    attn_mma<<<dim3(B_ * NW_, NH_), 128>>>(pqh, pkh, pvh, table, pch);

    // 4) output projection + reverse/un-shift + residual -> g_hs
    dim3 gp(TOK_ / BM, C_ / BN);
    gemm_h<<<gp, 256, GSMEM>>>(pch, who, bo, hidden, phs, C_, C_, 4, nullptr, nullptr);

    // 5) LN2 (plain) -> g_ah
    ln_kernel<<<TOK_, 128>>>(phs, ln2_g, ln2_b, pah, 0);

    // 6) FFN1 + GELU -> g_fh
    gemm_h<<<dim3(TOK_ / BM, FF_ / BN), 256, GSMEM>>>(
        pah, wh1, b1, nullptr, pfh, FF_, C_, 1, nullptr, nullptr);

    // 7) FFN2 + residual -> out
    gemm_h<<<gp, 256, GSMEM>>>(pfh, wh2, b2, phs, out, C_, FF_, 2, nullptr, nullptr);
}